// round 1
// baseline (speedup 1.0000x reference)
#include <cuda_runtime.h>
#include <cuda_bf16.h>
#include <math.h>

#define Bb   4
#define NPM  200
#define NVM  1500
#define D    512
#define Hh   8
#define DFF  2048
#define NL   3
#define Ss   (NPM + NVM + 2)   // 1702
#define DH   64
#define MROWS (Bb * Ss)        // 6808
#define COV  16

// ---------------- scratch (device globals; no allocation allowed) ----------
__device__ float g_x  [MROWS * D];
__device__ float g_h  [MROWS * D];
__device__ float g_qkv[MROWS * 3 * D];
__device__ float g_ao [MROWS * D];
__device__ float g_ffn[(size_t)MROWS * DFF];

// ---------------- embed: build x = [tok0 | pm@pmW+b | vm@vmW+b | -1] -------
__global__ void embed_kernel(const float* __restrict__ vm, const float* __restrict__ ns,
                             const float* __restrict__ pm,
                             const float* __restrict__ pmW, const float* __restrict__ pmb,
                             const float* __restrict__ vmW, const float* __restrict__ vmb,
                             float* __restrict__ x) {
    int row = blockIdx.x;
    int b = row / Ss, pos = row % Ss;
    float* out = x + (size_t)row * D;
    int tid = threadIdx.x;                 // 128 threads
    __shared__ float sin_[COV];

    if (pos == 0) {
        float v = ns[b];
        for (int c = tid; c < D; c += 128) out[c] = v;
        return;
    }
    if (pos == Ss - 1) {
        for (int c = tid; c < D; c += 128) out[c] = -1.0f;
        return;
    }
    const float* inr; const float* Wp; const float* bp;
    if (pos <= NPM) { inr = pm + ((size_t)b * NPM + (pos - 1)) * COV; Wp = pmW; bp = pmb; }
    else            { inr = vm + ((size_t)b * NVM + (pos - 1 - NPM)) * COV; Wp = vmW; bp = vmb; }
    if (tid < COV) sin_[tid] = inr[tid];
    __syncthreads();
    for (int c = tid; c < D; c += 128) {
        float acc = bp[c];
        #pragma unroll
        for (int k = 0; k < COV; k++) acc += sin_[k] * Wp[k * D + c];
        out[c] = acc;
    }
}

// ---------------- layernorm (two-pass, row of 512, 256 threads) ------------
__global__ void ln_kernel(const float* __restrict__ x, float* __restrict__ o,
                          const float* __restrict__ gamma, const float* __restrict__ beta) {
    int row = blockIdx.x;
    const float* xr = x + (size_t)row * D;
    int tid = threadIdx.x;
    float v0 = xr[tid], v1 = xr[tid + 256];
    __shared__ float red[8], red2[8];

    float s = v0 + v1;
    #pragma unroll
    for (int off = 16; off; off >>= 1) s += __shfl_xor_sync(0xFFFFFFFFu, s, off);
    if ((tid & 31) == 0) red[tid >> 5] = s;
    __syncthreads();
    float mean = 0.f;
    #pragma unroll
    for (int i = 0; i < 8; i++) mean += red[i];
    mean *= (1.0f / D);

    float d0 = v0 - mean, d1 = v1 - mean;
    float sq = d0 * d0 + d1 * d1;
    #pragma unroll
    for (int off = 16; off; off >>= 1) sq += __shfl_xor_sync(0xFFFFFFFFu, sq, off);
    if ((tid & 31) == 0) red2[tid >> 5] = sq;
    __syncthreads();
    float var = 0.f;
    #pragma unroll
    for (int i = 0; i < 8; i++) var += red2[i];
    var *= (1.0f / D);
    float inv = rsqrtf(var + 1e-5f);

    float* orow = o + (size_t)row * D;
    orow[tid]       = d0 * inv * gamma[tid]       + beta[tid];
    orow[tid + 256] = d1 * inv * gamma[tid + 256] + beta[tid + 256];
}

// ---------------- tiled SGEMM: C = act(A@W + bias) [+ resid] ---------------
// A: (M,K) row-major, W: (K,N) row-major. 64x64 tile, BK=16, 256 thr, 4x4/thr.
__global__ __launch_bounds__(256)
void sgemm_kernel(const float* __restrict__ A, const float* __restrict__ W,
                  const float* __restrict__ bias, const float* __restrict__ resid,
                  float* __restrict__ C, int M, int K, int N, int act) {
    __shared__ float As[16][64];
    __shared__ float Ws[16][64];
    int tid = threadIdx.x;
    int tx = tid & 15, ty = tid >> 4;
    int row0 = blockIdx.y * 64, col0 = blockIdx.x * 64;

    float acc[4][4];
    #pragma unroll
    for (int i = 0; i < 4; i++)
        #pragma unroll
        for (int j = 0; j < 4; j++) acc[i][j] = 0.f;

    int ar = tid >> 2, ac = (tid & 3) * 4;   // A tile load: 64x16
    int wr = tid >> 4, wc = (tid & 15) * 4;  // W tile load: 16x64
    int grow = row0 + ar;

    for (int kb = 0; kb < K; kb += 16) {
        float4 av;
        if (grow < M) av = *(const float4*)&A[(size_t)grow * K + kb + ac];
        else          av = make_float4(0.f, 0.f, 0.f, 0.f);
        As[ac + 0][ar] = av.x; As[ac + 1][ar] = av.y;
        As[ac + 2][ar] = av.z; As[ac + 3][ar] = av.w;
        *(float4*)&Ws[wr][wc] = *(const float4*)&W[(size_t)(kb + wr) * N + col0 + wc];
        __syncthreads();
        #pragma unroll
        for (int kk = 0; kk < 16; kk++) {
            float4 a = *(const float4*)&As[kk][ty * 4];
            float4 w = *(const float4*)&Ws[kk][tx * 4];
            acc[0][0] += a.x * w.x; acc[0][1] += a.x * w.y; acc[0][2] += a.x * w.z; acc[0][3] += a.x * w.w;
            acc[1][0] += a.y * w.x; acc[1][1] += a.y * w.y; acc[1][2] += a.y * w.z; acc[1][3] += a.y * w.w;
            acc[2][0] += a.z * w.x; acc[2][1] += a.z * w.y; acc[2][2] += a.z * w.z; acc[2][3] += a.z * w.w;
            acc[3][0] += a.w * w.x; acc[3][1] += a.w * w.y; acc[3][2] += a.w * w.z; acc[3][3] += a.w * w.w;
        }
        __syncthreads();
    }

    #pragma unroll
    for (int i = 0; i < 4; i++) {
        int row = row0 + ty * 4 + i;
        if (row >= M) continue;
        #pragma unroll
        for (int j = 0; j < 4; j++) {
            int col = col0 + tx * 4 + j;
            float v = acc[i][j] + bias[col];
            if (act == 1) v = 0.5f * v * (1.0f + erff(v * 0.70710678118654752f));
            if (resid) v += resid[(size_t)row * N + col];
            C[(size_t)row * N + col] = v;
        }
    }
}

// ---------------- attention ------------------------------------------------
// grid (ceil(S/16), H, B), 256 threads. q tile of 16 in regs, K/V chunks of
// 128 in smem, scores (16 x S) in dynamic smem, 2-pass softmax, PV pass.
#define SSTR 1704
#define KCH  128
#define ATTN_SMEM ((16 * SSTR + KCH * 64) * (int)sizeof(float))

__global__ __launch_bounds__(256)
void attn_kernel(const float* __restrict__ qkv, const int* __restrict__ rel,
                 const unsigned char* __restrict__ vmmask, float* __restrict__ ao) {
    extern __shared__ float sm[];
    float* sc  = sm;               // 16 * SSTR scores/probs
    float* skv = sm + 16 * SSTR;   // KCH * 64 K or V chunk
    __shared__ int   relq[16];
    __shared__ float ssum[16];

    int b = blockIdx.z, h = blockIdx.y;
    int q0 = blockIdx.x * 16;
    int tid = threadIdx.x;
    const float* qkvb = qkv + (size_t)b * Ss * (3 * D);
    const int* relb = rel + b * (NPM + NVM);
    const unsigned char* mb = vmmask + b * NVM;

    if (tid < 16) {
        int q = q0 + tid;
        relq[tid] = (q >= 1 && q <= Ss - 2) ? relb[q - 1] : -1;
    }

    int qi = tid & 15;
    int qg = q0 + qi;
    int qclamp = qg < Ss ? qg : Ss - 1;
    float4 qreg[16];
    {
        const float* qp = qkvb + (size_t)qclamp * (3 * D) + h * DH;
        #pragma unroll
        for (int i = 0; i < 16; i++) qreg[i] = *(const float4*)(qp + i * 4);
    }
    __syncthreads();
    int myrelq = relq[qi];
    int kjb = (tid >> 4) * 8;

    // ---- pass 1: scores ----
    for (int k0 = 0; k0 < Ss; k0 += KCH) {
        int kc = min(KCH, Ss - k0);
        for (int f = tid; f < kc * 16; f += 256) {
            int kk = f >> 4, dv = f & 15;
            *(float4*)&skv[kk * 64 + dv * 4] =
                *(const float4*)(qkvb + (size_t)(k0 + kk) * (3 * D) + D + h * DH + dv * 4);
        }
        __syncthreads();
        #pragma unroll
        for (int r = 0; r < 8; r++) {
            int kj = kjb + r;
            if (kj < kc) {
                float acc = 0.f;
                #pragma unroll
                for (int dv = 0; dv < 16; dv++) {
                    float4 kv = *(const float4*)&skv[kj * 64 + dv * 4];
                    acc += qreg[dv].x * kv.x + qreg[dv].y * kv.y
                         + qreg[dv].z * kv.z + qreg[dv].w * kv.w;
                }
                int k = k0 + kj;
                int relk = (k >= 1 && k <= Ss - 2) ? relb[k - 1] : -1;
                bool pad = (k >= 1 + NPM && k <= Ss - 2) ? (mb[k - 1 - NPM] != 0) : false;
                bool msk = (myrelq != -1 && relk != -1 && myrelq != relk) || pad;
                sc[qi * SSTR + k] = msk ? -1e9f : acc * 0.125f;
            }
        }
        __syncthreads();
    }

    // ---- softmax (warp w handles rows w, w+8) ----
    int wpid = tid >> 5, lane = tid & 31;
    for (int rr = wpid; rr < 16; rr += 8) {
        float* row = sc + rr * SSTR;
        float mx = -1e30f;
        for (int k = lane; k < Ss; k += 32) mx = fmaxf(mx, row[k]);
        #pragma unroll
        for (int o = 16; o; o >>= 1) mx = fmaxf(mx, __shfl_xor_sync(0xFFFFFFFFu, mx, o));
        float sum = 0.f;
        for (int k = lane; k < Ss; k += 32) {
            float p = expf(row[k] - mx);
            row[k] = p;
            sum += p;
        }
        #pragma unroll
        for (int o = 16; o; o >>= 1) sum += __shfl_xor_sync(0xFFFFFFFFu, sum, o);
        if (lane == 0) ssum[rr] = sum;
    }
    __syncthreads();

    // ---- pass 2: PV ----
    int d = tid & 63;
    int qb = tid >> 6;  // 0..3 -> rows qb, qb+4, qb+8, qb+12
    float o0 = 0.f, o1 = 0.f, o2 = 0.f, o3 = 0.f;
    for (int k0 = 0; k0 < Ss; k0 += KCH) {
        int kc = min(KCH, Ss - k0);
        for (int f = tid; f < kc * 16; f += 256) {
            int kk = f >> 4, dv = f & 15;
            *(float4*)&skv[kk * 64 + dv * 4] =
                *(const float4*)(qkvb + (size_t)(k0 + kk) * (3 * D) + 2 * D + h * DH + dv * 4);
        }
        __syncthreads();
        for (int k = 0; k < kc; k++) {
            float v = skv[k * 64 + d];
            int kg = k0 + k;
            o0 += sc[(qb + 0)  * SSTR + kg] * v;
            o1 += sc[(qb + 4)  * SSTR + kg] * v;
            o2 += sc[(qb + 8)  * SSTR + kg] * v;
            o3 += sc[(qb + 12) * SSTR + kg] * v;
        }
        __syncthreads();
    }
    float os[4] = {o0, o1, o2, o3};
    #pragma unroll
    for (int rr = 0; rr < 4; rr++) {
        int qq = qb + rr * 4;
        int q = q0 + qq;
        if (q < Ss) ao[((size_t)b * Ss + q) * D + h * DH + d] = os[rr] / ssum[qq];
    }
}

// ---------------- head: score rows + critic --------------------------------
__global__ void head_kernel(const float* __restrict__ x,
                            const float* __restrict__ outW, const float* __restrict__ outb,
                            const float* __restrict__ crW,  const float* __restrict__ crb,
                            float* __restrict__ out) {
    int r = blockIdx.x;
    int tid = threadIdx.x;  // 128
    const float* w; const float* xr; float bias; int oidx;
    if (r < Bb * NVM) {
        int b = r / NVM, i = r % NVM;
        xr = x + ((size_t)b * Ss + 1 + NPM + i) * D;
        w = outW; bias = outb[0]; oidx = r;
    } else {
        int b = r - Bb * NVM;
        xr = x + ((size_t)b * Ss + Ss - 1) * D;
        w = crW; bias = crb[0]; oidx = Bb * NVM + b;
    }
    float s = 0.f;
    for (int c = tid; c < D; c += 128) s += xr[c] * w[c];
    #pragma unroll
    for (int o = 16; o; o >>= 1) s += __shfl_xor_sync(0xFFFFFFFFu, s, o);
    __shared__ float red[4];
    if ((tid & 31) == 0) red[tid >> 5] = s;
    __syncthreads();
    if (tid == 0) out[oidx] = red[0] + red[1] + red[2] + red[3] + bias;
}

// ---------------- launch ---------------------------------------------------
extern "C" void kernel_launch(void* const* d_in, const int* in_sizes, int n_in,
                              void* d_out, int out_size) {
    const float* vm_states = (const float*)d_in[0];
    const float* num_step  = (const float*)d_in[1];
    const float* pm_states = (const float*)d_in[2];
    const int*   rel       = (const int*)d_in[3];
    const unsigned char* vmmask = (const unsigned char*)d_in[4];
    const float* pm_W = (const float*)d_in[5];
    const float* pm_b = (const float*)d_in[6];
    const float* vm_W = (const float*)d_in[7];
    const float* vm_b = (const float*)d_in[8];
    const float* ln1_s = (const float*)d_in[9];
    const float* ln1_b = (const float*)d_in[10];
    const float* Wqkv = (const float*)d_in[11];
    const float* bqkv = (const float*)d_in[12];
    const float* Wo   = (const float*)d_in[13];
    const float* bo   = (const float*)d_in[14];
    const float* ln2_s = (const float*)d_in[15];
    const float* ln2_b = (const float*)d_in[16];
    const float* W1 = (const float*)d_in[17];
    const float* b1 = (const float*)d_in[18];
    const float* W2 = (const float*)d_in[19];
    const float* b2 = (const float*)d_in[20];
    const float* out_W = (const float*)d_in[21];
    const float* out_b = (const float*)d_in[22];
    const float* cr_W  = (const float*)d_in[23];
    const float* cr_b  = (const float*)d_in[24];

    float *xp, *hp, *qkvp, *aop, *ffnp;
    cudaGetSymbolAddress((void**)&xp,   g_x);
    cudaGetSymbolAddress((void**)&hp,   g_h);
    cudaGetSymbolAddress((void**)&qkvp, g_qkv);
    cudaGetSymbolAddress((void**)&aop,  g_ao);
    cudaGetSymbolAddress((void**)&ffnp, g_ffn);

    cudaFuncSetAttribute(attn_kernel, cudaFuncAttributeMaxDynamicSharedMemorySize, ATTN_SMEM);

    embed_kernel<<<MROWS, 128>>>(vm_states, num_step, pm_states, pm_W, pm_b, vm_W, vm_b, xp);

    const int M = MROWS;
    dim3 gQKV(3 * D / 64, (M + 63) / 64);
    dim3 gO(D / 64, (M + 63) / 64);
    dim3 gF1(DFF / 64, (M + 63) / 64);
    dim3 gAttn((Ss + 15) / 16, Hh, Bb);

    for (int l = 0; l < NL; l++) {
        ln_kernel<<<M, 256>>>(xp, hp, ln1_s + l * D, ln1_b + l * D);
        sgemm_kernel<<<gQKV, 256>>>(hp, Wqkv + (size_t)l * D * 3 * D, bqkv + l * 3 * D,
                                    nullptr, qkvp, M, D, 3 * D, 0);
        attn_kernel<<<gAttn, 256, ATTN_SMEM>>>(qkvp, rel, vmmask, aop);
        sgemm_kernel<<<gO, 256>>>(aop, Wo + (size_t)l * D * D, bo + l * D,
                                  xp, xp, M, D, D, 0);
        ln_kernel<<<M, 256>>>(xp, hp, ln2_s + l * D, ln2_b + l * D);
        sgemm_kernel<<<gF1, 256>>>(hp, W1 + (size_t)l * D * DFF, b1 + l * DFF,
                                   nullptr, ffnp, M, D, DFF, 1);
        sgemm_kernel<<<gO, 256>>>(ffnp, W2 + (size_t)l * DFF * D, b2 + l * D,
                                  xp, xp, M, DFF, D, 0);
    }

    head_kernel<<<Bb * NVM + Bb, 128>>>(xp, out_W, out_b, cr_W, cr_b, (float*)d_out);
}

// round 2
// speedup vs baseline: 2.9781x; 2.9781x over previous
#include <cuda_runtime.h>
#include <cuda_bf16.h>
#include <math.h>

#define Bb   4
#define NPM  200
#define NVM  1500
#define D    512
#define Hh   8
#define DFF  2048
#define NL   3
#define Ss   (NPM + NVM + 2)   // 1702
#define DH   64
#define MROWS (Bb * Ss)        // 6808
#define COV  16
#define NINNER (NPM + NVM)     // 1700

// ---------------- scratch (device globals; no allocation allowed) ----------
__device__ float g_x  [MROWS * D];
__device__ float g_h  [MROWS * D];
__device__ float g_qkv[MROWS * 3 * D];
__device__ float g_ao [MROWS * D];
__device__ float g_ffn[(size_t)MROWS * DFF];

// sparse-attention structures
__device__ int g_gstart[Bb][NPM + 1];   // group offsets; [NPM] = total
__device__ int g_klist [Bb][NINNER];    // key positions (1..Ss-2), grouped by rel

// dense-row split-KV partials: [b][qi(0/1)][h][chunk]{m, l, acc[64]}
#define DCH 128
#define NCHUNK ((Ss + DCH - 1) / DCH)   // 14
__device__ float g_part[Bb][2][Hh][NCHUNK][66];

// ---------------- embed ----------------------------------------------------
__global__ void embed_kernel(const float* __restrict__ vm, const float* __restrict__ ns,
                             const float* __restrict__ pm,
                             const float* __restrict__ pmW, const float* __restrict__ pmb,
                             const float* __restrict__ vmW, const float* __restrict__ vmb,
                             float* __restrict__ x) {
    int row = blockIdx.x;
    int b = row / Ss, pos = row % Ss;
    float* out = x + (size_t)row * D;
    int tid = threadIdx.x;                 // 128 threads
    __shared__ float sin_[COV];

    if (pos == 0) {
        float v = ns[b];
        for (int c = tid; c < D; c += 128) out[c] = v;
        return;
    }
    if (pos == Ss - 1) {
        for (int c = tid; c < D; c += 128) out[c] = -1.0f;
        return;
    }
    const float* inr; const float* Wp; const float* bp;
    if (pos <= NPM) { inr = pm + ((size_t)b * NPM + (pos - 1)) * COV; Wp = pmW; bp = pmb; }
    else            { inr = vm + ((size_t)b * NVM + (pos - 1 - NPM)) * COV; Wp = vmW; bp = vmb; }
    if (tid < COV) sin_[tid] = inr[tid];
    __syncthreads();
    for (int c = tid; c < D; c += 128) {
        float acc = bp[c];
        #pragma unroll
        for (int k = 0; k < COV; k++) acc += sin_[k] * Wp[k * D + c];
        out[c] = acc;
    }
}

// ---------------- layernorm -------------------------------------------------
__global__ void ln_kernel(const float* __restrict__ x, float* __restrict__ o,
                          const float* __restrict__ gamma, const float* __restrict__ beta) {
    int row = blockIdx.x;
    const float* xr = x + (size_t)row * D;
    int tid = threadIdx.x;
    float v0 = xr[tid], v1 = xr[tid + 256];
    __shared__ float red[8], red2[8];

    float s = v0 + v1;
    #pragma unroll
    for (int off = 16; off; off >>= 1) s += __shfl_xor_sync(0xFFFFFFFFu, s, off);
    if ((tid & 31) == 0) red[tid >> 5] = s;
    __syncthreads();
    float mean = 0.f;
    #pragma unroll
    for (int i = 0; i < 8; i++) mean += red[i];
    mean *= (1.0f / D);

    float d0 = v0 - mean, d1 = v1 - mean;
    float sq = d0 * d0 + d1 * d1;
    #pragma unroll
    for (int off = 16; off; off >>= 1) sq += __shfl_xor_sync(0xFFFFFFFFu, sq, off);
    if ((tid & 31) == 0) red2[tid >> 5] = sq;
    __syncthreads();
    float var = 0.f;
    #pragma unroll
    for (int i = 0; i < 8; i++) var += red2[i];
    var *= (1.0f / D);
    float inv = rsqrtf(var + 1e-5f);

    float* orow = o + (size_t)row * D;
    orow[tid]       = d0 * inv * gamma[tid]       + beta[tid];
    orow[tid + 256] = d1 * inv * gamma[tid + 256] + beta[tid + 256];
}

// ---------------- 128x128 double-buffered SGEMM ----------------------------
// C = act(A@W + bias) [+ resid].  A:(M,K) rm, W:(K,N) rm. 256 thr, 8x8/thr.
__global__ __launch_bounds__(256)
void sgemm_kernel(const float* __restrict__ A, const float* __restrict__ W,
                  const float* __restrict__ bias, const float* __restrict__ resid,
                  float* __restrict__ C, int M, int K, int N, int act) {
    __shared__ float As[2][8][128];
    __shared__ float Ws[2][8][128];
    int tid = threadIdx.x;
    int row0 = blockIdx.y * 128, col0 = blockIdx.x * 128;

    int arow = tid >> 1, acol = (tid & 1) * 4;
    int wrow = tid >> 5, wcol = (tid & 31) * 4;
    int tx = tid & 15, ty = tid >> 4;

    float acc[8][8];
    #pragma unroll
    for (int i = 0; i < 8; i++)
        #pragma unroll
        for (int j = 0; j < 8; j++) acc[i][j] = 0.f;

    int grow = row0 + arow;
    bool aval = grow < M;
    const float* Aptr = A + (size_t)(aval ? grow : 0) * K + acol;
    const float* Wptr = W + (size_t)wrow * N + col0 + wcol;

    float4 areg = aval ? *(const float4*)Aptr : make_float4(0.f, 0.f, 0.f, 0.f);
    float4 wreg = *(const float4*)Wptr;
    As[0][acol + 0][arow] = areg.x; As[0][acol + 1][arow] = areg.y;
    As[0][acol + 2][arow] = areg.z; As[0][acol + 3][arow] = areg.w;
    *(float4*)&Ws[0][wrow][wcol] = wreg;
    __syncthreads();

    int nt = K >> 3;
    for (int t = 0; t < nt; t++) {
        int cur = t & 1, nxt = cur ^ 1;
        if (t + 1 < nt) {
            areg = aval ? *(const float4*)(Aptr + (size_t)(t + 1) * 8)
                        : make_float4(0.f, 0.f, 0.f, 0.f);
            wreg = *(const float4*)(Wptr + (size_t)(t + 1) * 8 * N);
        }
        #pragma unroll
        for (int kk = 0; kk < 8; kk++) {
            float a[8], bvr[8];
            *(float4*)&a[0]   = *(const float4*)&As[cur][kk][ty * 4];
            *(float4*)&a[4]   = *(const float4*)&As[cur][kk][64 + ty * 4];
            *(float4*)&bvr[0] = *(const float4*)&Ws[cur][kk][tx * 4];
            *(float4*)&bvr[4] = *(const float4*)&Ws[cur][kk][64 + tx * 4];
            #pragma unroll
            for (int i = 0; i < 8; i++)
                #pragma unroll
                for (int j = 0; j < 8; j++) acc[i][j] += a[i] * bvr[j];
        }
        if (t + 1 < nt) {
            As[nxt][acol + 0][arow] = areg.x; As[nxt][acol + 1][arow] = areg.y;
            As[nxt][acol + 2][arow] = areg.z; As[nxt][acol + 3][arow] = areg.w;
            *(float4*)&Ws[nxt][wrow][wcol] = wreg;
            __syncthreads();
        }
    }

    #pragma unroll
    for (int i = 0; i < 8; i++) {
        int ri = (i < 4) ? (ty * 4 + i) : (64 + ty * 4 + i - 4);
        int row = row0 + ri;
        if (row >= M) continue;
        #pragma unroll
        for (int j = 0; j < 8; j++) {
            int cj = (j < 4) ? (tx * 4 + j) : (64 + tx * 4 + j - 4);
            int col = col0 + cj;
            float v = acc[i][j] + bias[col];
            if (act == 1) v = 0.5f * v * (1.0f + erff(v * 0.70710678118654752f));
            if (resid) v += resid[(size_t)row * N + col];
            C[(size_t)row * N + col] = v;
        }
    }
}

// ---------------- build group lists (counting sort per batch) --------------
__global__ void build_groups(const int* __restrict__ rel,
                             const unsigned char* __restrict__ vmmask) {
    int b = blockIdx.x;
    __shared__ int cnt[NPM];
    __shared__ int off[NPM];
    int tid = threadIdx.x;  // 256
    for (int i = tid; i < NPM; i += 256) cnt[i] = 0;
    __syncthreads();
    const int* rb = rel + b * NINNER;
    const unsigned char* pb = vmmask + b * NVM;
    for (int i = tid; i < NINNER; i += 256) {
        bool padded = (i >= NPM) && (pb[i - NPM] != 0);
        if (!padded) atomicAdd(&cnt[rb[i]], 1);
    }
    __syncthreads();
    if (tid == 0) {
        int s = 0;
        for (int r = 0; r < NPM; r++) {
            off[r] = s;
            g_gstart[b][r] = s;
            s += cnt[r];
        }
        g_gstart[b][NPM] = s;
    }
    __syncthreads();
    for (int i = tid; i < NINNER; i += 256) {
        bool padded = (i >= NPM) && (pb[i - NPM] != 0);
        if (!padded) {
            int p = atomicAdd(&off[rb[i]], 1);
            g_klist[b][p] = i + 1;           // key position in full sequence
        }
    }
}

// ---------------- sparse attention: warp per (q, h), inner queries ---------
__global__ __launch_bounds__(256)
void attn_sparse(const float* __restrict__ qkv, const int* __restrict__ rel,
                 float* __restrict__ ao) {
    int q = blockIdx.x, b = blockIdx.y;
    if (q == 0 || q == Ss - 1) return;     // dense rows handled by split-KV path
    int h = threadIdx.x >> 5, lane = threadIdx.x & 31;

    const float* qkvb = qkv + (size_t)b * Ss * (3 * D);
    float2 qv = *(const float2*)(qkvb + (size_t)q * (3 * D) + h * DH + lane * 2);

    int r = rel[b * NINNER + (q - 1)];
    int kstart = g_gstart[b][r];
    int kend   = g_gstart[b][r + 1];

    float m = -1e30f, l = 0.f;
    float2 acc = make_float2(0.f, 0.f);

    // keys: 0, group segment, Ss-1
    for (int it = -1; it <= kend - kstart; it++) {
        int k;
        if (it == -1) k = 0;
        else if (it == kend - kstart) k = Ss - 1;
        else k = g_klist[b][kstart + it];

        const float* kp = qkvb + (size_t)k * (3 * D) + D + h * DH + lane * 2;
        float2 kv = *(const float2*)kp;
        float s = qv.x * kv.x + qv.y * kv.y;
        #pragma unroll
        for (int o = 16; o; o >>= 1) s += __shfl_xor_sync(0xFFFFFFFFu, s, o);
        s *= 0.125f;
        float mn = fmaxf(m, s);
        float corr = expf(m - mn);
        float p = expf(s - mn);
        float2 vv = *(const float2*)(kp + D);
        l = l * corr + p;
        acc.x = acc.x * corr + p * vv.x;
        acc.y = acc.y * corr + p * vv.y;
        m = mn;
    }
    float inv = 1.0f / l;
    float2 outv = make_float2(acc.x * inv, acc.y * inv);
    *(float2*)(ao + ((size_t)b * Ss + q) * D + h * DH + lane * 2) = outv;
}

// ---------------- dense rows (q=0, q=Ss-1): split-KV partials --------------
__global__ __launch_bounds__(256)
void attn_dense_part(const float* __restrict__ qkv,
                     const unsigned char* __restrict__ vmmask) {
    int chunk = blockIdx.x, qi = blockIdx.y, b = blockIdx.z;
    int h = threadIdx.x >> 5, lane = threadIdx.x & 31;
    int q = (qi == 0) ? 0 : Ss - 1;

    const float* qkvb = qkv + (size_t)b * Ss * (3 * D);
    const unsigned char* pb = vmmask + b * NVM;
    float2 qv = *(const float2*)(qkvb + (size_t)q * (3 * D) + h * DH + lane * 2);

    int k0 = chunk * DCH, k1 = min(Ss, k0 + DCH);
    float m = -1e30f, l = 0.f;
    float2 acc = make_float2(0.f, 0.f);

    for (int k = k0; k < k1; k++) {
        bool padded = (k >= 1 + NPM && k <= Ss - 2) && (pb[k - 1 - NPM] != 0);
        if (padded) continue;
        const float* kp = qkvb + (size_t)k * (3 * D) + D + h * DH + lane * 2;
        float2 kv = *(const float2*)kp;
        float s = qv.x * kv.x + qv.y * kv.y;
        #pragma unroll
        for (int o = 16; o; o >>= 1) s += __shfl_xor_sync(0xFFFFFFFFu, s, o);
        s *= 0.125f;
        float mn = fmaxf(m, s);
        float corr = expf(m - mn);
        float p = expf(s - mn);
        float2 vv = *(const float2*)(kp + D);
        l = l * corr + p;
        acc.x = acc.x * corr + p * vv.x;
        acc.y = acc.y * corr + p * vv.y;
        m = mn;
    }
    float* part = g_part[b][qi][h][chunk];
    if (lane == 0) { part[0] = m; part[1] = l; }
    part[2 + lane * 2]     = acc.x;
    part[2 + lane * 2 + 1] = acc.y;
}

__global__ __launch_bounds__(256)
void attn_dense_combine(float* __restrict__ ao) {
    int qi = blockIdx.x & 1, b = blockIdx.x >> 1;
    int h = threadIdx.x >> 5, lane = threadIdx.x & 31;
    int q = (qi == 0) ? 0 : Ss - 1;

    float M = -1e30f;
    #pragma unroll
    for (int c = 0; c < NCHUNK; c++) M = fmaxf(M, g_part[b][qi][h][c][0]);
    float L = 0.f;
    float2 acc = make_float2(0.f, 0.f);
    #pragma unroll
    for (int c = 0; c < NCHUNK; c++) {
        const float* part = g_part[b][qi][h][c];
        float w = expf(part[0] - M);
        L += part[1] * w;
        acc.x += w * part[2 + lane * 2];
        acc.y += w * part[2 + lane * 2 + 1];
    }
    float inv = 1.0f / L;
    float2 outv = make_float2(acc.x * inv, acc.y * inv);
    *(float2*)(ao + ((size_t)b * Ss + q) * D + h * DH + lane * 2) = outv;
}

// ---------------- head -----------------------------------------------------
__global__ void head_kernel(const float* __restrict__ x,
                            const float* __restrict__ outW, const float* __restrict__ outb,
                            const float* __restrict__ crW,  const float* __restrict__ crb,
                            float* __restrict__ out) {
    int r = blockIdx.x;
    int tid = threadIdx.x;  // 128
    const float* w; const float* xr; float bias; int oidx;
    if (r < Bb * NVM) {
        int b = r / NVM, i = r % NVM;
        xr = x + ((size_t)b * Ss + 1 + NPM + i) * D;
        w = outW; bias = outb[0]; oidx = r;
    } else {
        int b = r - Bb * NVM;
        xr = x + ((size_t)b * Ss + Ss - 1) * D;
        w = crW; bias = crb[0]; oidx = Bb * NVM + b;
    }
    float s = 0.f;
    for (int c = tid; c < D; c += 128) s += xr[c] * w[c];
    #pragma unroll
    for (int o = 16; o; o >>= 1) s += __shfl_xor_sync(0xFFFFFFFFu, s, o);
    __shared__ float red[4];
    if ((tid & 31) == 0) red[tid >> 5] = s;
    __syncthreads();
    if (tid == 0) out[oidx] = red[0] + red[1] + red[2] + red[3] + bias;
}

// ---------------- launch ---------------------------------------------------
extern "C" void kernel_launch(void* const* d_in, const int* in_sizes, int n_in,
                              void* d_out, int out_size) {
    const float* vm_states = (const float*)d_in[0];
    const float* num_step  = (const float*)d_in[1];
    const float* pm_states = (const float*)d_in[2];
    const int*   rel       = (const int*)d_in[3];
    const unsigned char* vmmask = (const unsigned char*)d_in[4];
    const float* pm_W = (const float*)d_in[5];
    const float* pm_b = (const float*)d_in[6];
    const float* vm_W = (const float*)d_in[7];
    const float* vm_b = (const float*)d_in[8];
    const float* ln1_s = (const float*)d_in[9];
    const float* ln1_b = (const float*)d_in[10];
    const float* Wqkv = (const float*)d_in[11];
    const float* bqkv = (const float*)d_in[12];
    const float* Wo   = (const float*)d_in[13];
    const float* bo   = (const float*)d_in[14];
    const float* ln2_s = (const float*)d_in[15];
    const float* ln2_b = (const float*)d_in[16];
    const float* W1 = (const float*)d_in[17];
    const float* b1 = (const float*)d_in[18];
    const float* W2 = (const float*)d_in[19];
    const float* b2 = (const float*)d_in[20];
    const float* out_W = (const float*)d_in[21];
    const float* out_b = (const float*)d_in[22];
    const float* cr_W  = (const float*)d_in[23];
    const float* cr_b  = (const float*)d_in[24];

    float *xp, *hp, *qkvp, *aop, *ffnp;
    cudaGetSymbolAddress((void**)&xp,   g_x);
    cudaGetSymbolAddress((void**)&hp,   g_h);
    cudaGetSymbolAddress((void**)&qkvp, g_qkv);
    cudaGetSymbolAddress((void**)&aop,  g_ao);
    cudaGetSymbolAddress((void**)&ffnp, g_ffn);

    embed_kernel<<<MROWS, 128>>>(vm_states, num_step, pm_states, pm_W, pm_b, vm_W, vm_b, xp);
    build_groups<<<Bb, 256>>>(rel, vmmask);

    const int M = MROWS;
    dim3 gQKV(3 * D / 128, (M + 127) / 128);
    dim3 gO(D / 128, (M + 127) / 128);
    dim3 gF1(DFF / 128, (M + 127) / 128);
    dim3 gSp(Ss, Bb);
    dim3 gDp(NCHUNK, 2, Bb);

    for (int l = 0; l < NL; l++) {
        ln_kernel<<<M, 256>>>(xp, hp, ln1_s + l * D, ln1_b + l * D);
        sgemm_kernel<<<gQKV, 256>>>(hp, Wqkv + (size_t)l * D * 3 * D, bqkv + l * 3 * D,
                                    nullptr, qkvp, M, D, 3 * D, 0);
        attn_sparse<<<gSp, 256>>>(qkvp, rel, aop);
        attn_dense_part<<<gDp, 256>>>(qkvp, vmmask);
        attn_dense_combine<<<2 * Bb, 256>>>(aop);
        sgemm_kernel<<<gO, 256>>>(aop, Wo + (size_t)l * D * D, bo + l * D,
                                  xp, xp, M, D, D, 0);
        ln_kernel<<<M, 256>>>(xp, hp, ln2_s + l * D, ln2_b + l * D);
        sgemm_kernel<<<gF1, 256>>>(hp, W1 + (size_t)l * D * DFF, b1 + l * DFF,
                                   nullptr, ffnp, M, D, DFF, 1);
        sgemm_kernel<<<gO, 256>>>(ffnp, W2 + (size_t)l * DFF * D, b2 + l * D,
                                  xp, xp, M, DFF, D, 0);
    }

    head_kernel<<<Bb * NVM + Bb, 128>>>(xp, out_W, out_b, cr_W, cr_b, (float*)d_out);
}

// round 5
// speedup vs baseline: 5.7293x; 1.9238x over previous
#include <cuda_runtime.h>
#include <cuda_bf16.h>
#include <math.h>
#include <stdint.h>

#define Bb   4
#define NPM  200
#define NVM  1500
#define D    512
#define Hh   8
#define DFF  2048
#define NL   3
#define Ss   (NPM + NVM + 2)   // 1702
#define DH   64
#define MROWS (Bb * Ss)        // 6808
#define COV  16
#define NINNER (NPM + NVM)     // 1700

// ---------------- scratch (device globals; no allocation allowed) ----------
__device__ float g_x  [MROWS * D];
__device__ float g_h  [MROWS * D];
__device__ float g_qkv[MROWS * 3 * D];
__device__ float g_ao [MROWS * D];
__device__ float g_ffn[(size_t)MROWS * DFF];

// split+transposed weights (bf16 hi/lo), per layer [qkv_t | wo_t | w1_t | w2_t]
#define OQKV 0
#define OWO  786432
#define OW1  1048576
#define OW2  2097152
#define PERL 3145728
__device__ __nv_bfloat16 g_wh[(size_t)NL * PERL];
__device__ __nv_bfloat16 g_wl[(size_t)NL * PERL];

// sparse-attention structures
__device__ int g_gstart[Bb][NPM + 1];
__device__ int g_klist [Bb][NINNER];

#define DCH 128
#define NCHUNK ((Ss + DCH - 1) / DCH)   // 14
__device__ float g_part[Bb][2][Hh][NCHUNK][66];

// ---------------- helpers ---------------------------------------------------
__device__ __forceinline__ uint32_t smem_u32(const void* p) {
    uint32_t a;
    asm("{ .reg .u64 t; cvta.to.shared.u64 t, %1; cvt.u32.u64 %0, t; }" : "=r"(a) : "l"(p));
    return a;
}
__device__ __forceinline__ uint32_t pkbf(float a, float b) {
    __nv_bfloat162 t = __floats2bfloat162_rn(a, b);
    return *reinterpret_cast<uint32_t*>(&t);
}
__device__ __forceinline__ void ldm_x4(uint32_t* r, uint32_t addr) {
    asm volatile("ldmatrix.sync.aligned.m8n8.x4.shared.b16 {%0,%1,%2,%3}, [%4];"
                 : "=r"(r[0]), "=r"(r[1]), "=r"(r[2]), "=r"(r[3]) : "r"(addr));
}
__device__ __forceinline__ void ldm_x2(uint32_t* r, uint32_t addr) {
    asm volatile("ldmatrix.sync.aligned.m8n8.x2.shared.b16 {%0,%1}, [%2];"
                 : "=r"(r[0]), "=r"(r[1]) : "r"(addr));
}
__device__ __forceinline__ void mma16816(float* c, const uint32_t* a, const uint32_t* b) {
    asm volatile("mma.sync.aligned.m16n8k16.row.col.f32.bf16.bf16.f32 "
                 "{%0,%1,%2,%3}, {%4,%5,%6,%7}, {%8,%9}, {%0,%1,%2,%3};"
                 : "+f"(c[0]), "+f"(c[1]), "+f"(c[2]), "+f"(c[3])
                 : "r"(a[0]), "r"(a[1]), "r"(a[2]), "r"(a[3]), "r"(b[0]), "r"(b[1]));
}

// ---------------- prep: W(K,N) fp32 -> bf16 hi/lo (N,K) --------------------
__global__ void prep_w(const float* __restrict__ W, __nv_bfloat16* __restrict__ Th,
                       __nv_bfloat16* __restrict__ Tl, int K, int N) {
    __shared__ float s[32][33];
    int n0 = blockIdx.x * 32, k0 = blockIdx.y * 32;
    int x = threadIdx.x, y = threadIdx.y;  // 32 x 8
    #pragma unroll
    for (int j = 0; j < 4; j++)
        s[y + 8 * j][x] = W[(size_t)(k0 + y + 8 * j) * N + n0 + x];
    __syncthreads();
    #pragma unroll
    for (int j = 0; j < 4; j++) {
        float v = s[x][y + 8 * j];
        __nv_bfloat16 h = __float2bfloat16(v);
        __nv_bfloat16 l = __float2bfloat16(v - __bfloat162float(h));
        size_t o = (size_t)(n0 + y + 8 * j) * K + k0 + x;
        Th[o] = h; Tl[o] = l;
    }
}

// ---------------- split-bf16 mma.sync GEMM ---------------------------------
// C = act(A @ B^T + bias) [+resid];  A:(M,K) rm fp32, Bh/Bl:(N,K) rm bf16.
// 128x128 tile, K chunks of 32, 256 thr = 8 warps (2m x 4n), warp 64x32.
// smem per stage: Ah/Al/Bh/Bl each 128 rows x 80B (64B data + 16B pad).
#define RSTRIDE 80
#define MATB  (128 * RSTRIDE)         // 10240
#define STAGE (4 * MATB)              // 40960
#define GSMEM (2 * STAGE)             // 81920

__global__ __launch_bounds__(256, 1)
void mma_gemm(const float* __restrict__ A, const __nv_bfloat16* __restrict__ Bhg,
              const __nv_bfloat16* __restrict__ Blg, const float* __restrict__ bias,
              const float* __restrict__ resid, float* __restrict__ C,
              int M, int K, int N, int act) {
    extern __shared__ char sm[];
    __shared__ float s_bias[128];
    int tid = threadIdx.x, wid = tid >> 5, lane = tid & 31;
    int row0 = blockIdx.y * 128, col0 = blockIdx.x * 128;
    int wm = wid >> 2, wn = wid & 3;           // warp tile: (wm*64, wn*32)
    uint32_t sbase = smem_u32(sm);

    if (tid < 128) s_bias[tid] = bias[col0 + tid];

    float acc[4][4][4];
    #pragma unroll
    for (int i = 0; i < 4; i++)
        #pragma unroll
        for (int j = 0; j < 4; j++)
            #pragma unroll
            for (int k = 0; k < 4; k++) acc[i][j][k] = 0.f;

    // staging regs
    float4 areg[4];
    uint4  bhreg[2], blreg[2];

    const int arow = tid >> 3, ac4 = (tid & 7) * 4;   // + i*32 rows
    const int brow = tid >> 2, bcb = (tid & 3) * 16;  // + i*64 rows, byte col

    // fragment smem addresses (lane-dependent)
    const int a_r = lane & 15, a_cb = (lane >> 4) * 16;
    const int b_r = lane & 7,  b_cb = ((lane >> 3) & 1) * 16;

    int nch = K >> 5;

    // ---- prologue: chunk 0 ----
    {
        #pragma unroll
        for (int i = 0; i < 4; i++) {
            int gr = row0 + arow + i * 32;
            areg[i] = (gr < M) ? *(const float4*)(A + (size_t)gr * K + ac4)
                               : make_float4(0.f, 0.f, 0.f, 0.f);
        }
        #pragma unroll
        for (int i = 0; i < 2; i++) {
            size_t go = (size_t)(col0 + brow + i * 64) * K + (bcb >> 1);
            bhreg[i] = *(const uint4*)(Bhg + go);
            blreg[i] = *(const uint4*)(Blg + go);
        }
        char* st = sm;
        #pragma unroll
        for (int i = 0; i < 4; i++) {
            float4 v = areg[i];
            uint2 h, l;
            float hx = __bfloat162float(__float2bfloat16(v.x));
            float hy = __bfloat162float(__float2bfloat16(v.y));
            float hz = __bfloat162float(__float2bfloat16(v.z));
            float hw = __bfloat162float(__float2bfloat16(v.w));
            h.x = pkbf(hx, hy); h.y = pkbf(hz, hw);
            l.x = pkbf(v.x - hx, v.y - hy); l.y = pkbf(v.z - hz, v.w - hw);
            int off = (arow + i * 32) * RSTRIDE + ac4 * 2;
            *(uint2*)(st + off)        = h;
            *(uint2*)(st + MATB + off) = l;
        }
        #pragma unroll
        for (int i = 0; i < 2; i++) {
            int off = (brow + i * 64) * RSTRIDE + bcb;
            *(uint4*)(st + 2 * MATB + off) = bhreg[i];
            *(uint4*)(st + 3 * MATB + off) = blreg[i];
        }
    }
    __syncthreads();

    for (int c = 0; c < nch; c++) {
        int kb = (c + 1) << 5;
        if (c + 1 < nch) {
            #pragma unroll
            for (int i = 0; i < 4; i++) {
                int gr = row0 + arow + i * 32;
                areg[i] = (gr < M) ? *(const float4*)(A + (size_t)gr * K + kb + ac4)
                                   : make_float4(0.f, 0.f, 0.f, 0.f);
            }
            #pragma unroll
            for (int i = 0; i < 2; i++) {
                size_t go = (size_t)(col0 + brow + i * 64) * K + kb + (bcb >> 1);
                bhreg[i] = *(const uint4*)(Bhg + go);
                blreg[i] = *(const uint4*)(Blg + go);
            }
        }

        // ---- compute chunk c ----
        uint32_t stA = sbase + (c & 1) * STAGE;
        uint32_t stB = stA + 2 * MATB;
        #pragma unroll
        for (int s = 0; s < 2; s++) {
            uint32_t ah[4][4], al[4][4], bh[4][2], bl[4][2];
            #pragma unroll
            for (int mt = 0; mt < 4; mt++) {
                uint32_t addr = stA + (wm * 64 + mt * 16 + a_r) * RSTRIDE + a_cb + s * 32;
                ldm_x4(ah[mt], addr);
                ldm_x4(al[mt], addr + MATB);
            }
            #pragma unroll
            for (int nt = 0; nt < 4; nt++) {
                uint32_t addr = stB + (wn * 32 + nt * 8 + b_r) * RSTRIDE + b_cb + s * 32;
                ldm_x2(bh[nt], addr);
                ldm_x2(bl[nt], addr + MATB);
            }
            #pragma unroll
            for (int mt = 0; mt < 4; mt++)
                #pragma unroll
                for (int nt = 0; nt < 4; nt++) {
                    mma16816(acc[mt][nt], ah[mt], bh[nt]);
                    mma16816(acc[mt][nt], ah[mt], bl[nt]);
                    mma16816(acc[mt][nt], al[mt], bh[nt]);
                }
        }

        if (c + 1 < nch) {
            __syncthreads();
            char* st = sm + ((c + 1) & 1) * STAGE;
            #pragma unroll
            for (int i = 0; i < 4; i++) {
                float4 v = areg[i];
                uint2 h, l;
                float hx = __bfloat162float(__float2bfloat16(v.x));
                float hy = __bfloat162float(__float2bfloat16(v.y));
                float hz = __bfloat162float(__float2bfloat16(v.z));
                float hw = __bfloat162float(__float2bfloat16(v.w));
                h.x = pkbf(hx, hy); h.y = pkbf(hz, hw);
                l.x = pkbf(v.x - hx, v.y - hy); l.y = pkbf(v.z - hz, v.w - hw);
                int off = (arow + i * 32) * RSTRIDE + ac4 * 2;
                *(uint2*)(st + off)        = h;
                *(uint2*)(st + MATB + off) = l;
            }
            #pragma unroll
            for (int i = 0; i < 2; i++) {
                int off = (brow + i * 64) * RSTRIDE + bcb;
                *(uint4*)(st + 2 * MATB + off) = bhreg[i];
                *(uint4*)(st + 3 * MATB + off) = blreg[i];
            }
            __syncthreads();
        }
    }

    // ---- epilogue ----
    int qrow = lane >> 2, qcol = (lane & 3) * 2;
    #pragma unroll
    for (int mt = 0; mt < 4; mt++) {
        #pragma unroll
        for (int half = 0; half < 2; half++) {
            int r = row0 + wm * 64 + mt * 16 + qrow + half * 8;
            if (r >= M) continue;
            #pragma unroll
            for (int nt = 0; nt < 4; nt++) {
                int cl = wn * 32 + nt * 8 + qcol;
                float v0 = acc[mt][nt][half * 2 + 0] + s_bias[cl];
                float v1 = acc[mt][nt][half * 2 + 1] + s_bias[cl + 1];
                if (act) {
                    v0 = 0.5f * v0 * (1.0f + erff(v0 * 0.707106781186547524f));
                    v1 = 0.5f * v1 * (1.0f + erff(v1 * 0.707106781186547524f));
                }
                size_t go = (size_t)r * N + col0 + cl;
                if (resid) {
                    float2 rv = *(const float2*)(resid + go);
                    v0 += rv.x; v1 += rv.y;
                }
                *(float2*)(C + go) = make_float2(v0, v1);
            }
        }
    }
}

// ---------------- embed ----------------------------------------------------
__global__ void embed_kernel(const float* __restrict__ vm, const float* __restrict__ ns,
                             const float* __restrict__ pm,
                             const float* __restrict__ pmW, const float* __restrict__ pmb,
                             const float* __restrict__ vmW, const float* __restrict__ vmb,
                             float* __restrict__ x) {
    int row = blockIdx.x;
    int b = row / Ss, pos = row % Ss;
    float* out = x + (size_t)row * D;
    int tid = threadIdx.x;
    __shared__ float sin_[COV];

    if (pos == 0) {
        float v = ns[b];
        for (int c = tid; c < D; c += 128) out[c] = v;
        return;
    }
    if (pos == Ss - 1) {
        for (int c = tid; c < D; c += 128) out[c] = -1.0f;
        return;
    }
    const float* inr; const float* Wp; const float* bp;
    if (pos <= NPM) { inr = pm + ((size_t)b * NPM + (pos - 1)) * COV; Wp = pmW; bp = pmb; }
    else            { inr = vm + ((size_t)b * NVM + (pos - 1 - NPM)) * COV; Wp = vmW; bp = vmb; }
    if (tid < COV) sin_[tid] = inr[tid];
    __syncthreads();
    for (int c = tid; c < D; c += 128) {
        float acc = bp[c];
        #pragma unroll
        for (int k = 0; k < COV; k++) acc += sin_[k] * Wp[k * D + c];
        out[c] = acc;
    }
}

// ---------------- layernorm -------------------------------------------------
__global__ void ln_kernel(const float* __restrict__ x, float* __restrict__ o,
                          const float* __restrict__ gamma, const float* __restrict__ beta) {
    int row = blockIdx.x;
    const float* xr = x + (size_t)row * D;
    int tid = threadIdx.x;
    float v0 = xr[tid], v1 = xr[tid + 256];
    __shared__ float red[8], red2[8];

    float s = v0 + v1;
    #pragma unroll
    for (int off = 16; off; off >>= 1) s += __shfl_xor_sync(0xFFFFFFFFu, s, off);
    if ((tid & 31) == 0) red[tid >> 5] = s;
    __syncthreads();
    float mean = 0.f;
    #pragma unroll
    for (int i = 0; i < 8; i++) mean += red[i];
    mean *= (1.0f / D);

    float d0 = v0 - mean, d1 = v1 - mean;
    float sq = d0 * d0 + d1 * d1;
    #pragma unroll
    for (int off = 16; off; off >>= 1) sq += __shfl_xor_sync(0xFFFFFFFFu, sq, off);
    if ((tid & 31) == 0) red2[tid >> 5] = sq;
    __syncthreads();
    float var = 0.f;
    #pragma unroll
    for (int i = 0; i < 8; i++) var += red2[i];
    var *= (1.0f / D);
    float inv = rsqrtf(var + 1e-5f);

    float* orow = o + (size_t)row * D;
    orow[tid]       = d0 * inv * gamma[tid]       + beta[tid];
    orow[tid + 256] = d1 * inv * gamma[tid + 256] + beta[tid + 256];
}

// ---------------- build group lists ----------------------------------------
__global__ void build_groups(const int* __restrict__ rel,
                             const unsigned char* __restrict__ vmmask) {
    int b = blockIdx.x;
    __shared__ int cnt[NPM];
    __shared__ int off[NPM];
    int tid = threadIdx.x;
    for (int i = tid; i < NPM; i += 256) cnt[i] = 0;
    __syncthreads();
    const int* rb = rel + b * NINNER;
    const unsigned char* pb = vmmask + b * NVM;
    for (int i = tid; i < NINNER; i += 256) {
        bool padded = (i >= NPM) && (pb[i - NPM] != 0);
        if (!padded) atomicAdd(&cnt[rb[i]], 1);
    }
    __syncthreads();
    if (tid == 0) {
        int s = 0;
        for (int r = 0; r < NPM; r++) {
            off[r] = s;
            g_gstart[b][r] = s;
            s += cnt[r];
        }
        g_gstart[b][NPM] = s;
    }
    __syncthreads();
    for (int i = tid; i < NINNER; i += 256) {
        bool padded = (i >= NPM) && (pb[i - NPM] != 0);
        if (!padded) {
            int p = atomicAdd(&off[rb[i]], 1);
            g_klist[b][p] = i + 1;
        }
    }
}

// ---------------- sparse attention -----------------------------------------
__global__ __launch_bounds__(256)
void attn_sparse(const float* __restrict__ qkv, const int* __restrict__ rel,
                 float* __restrict__ ao) {
    int q = blockIdx.x, b = blockIdx.y;
    if (q == 0 || q == Ss - 1) return;
    int h = threadIdx.x >> 5, lane = threadIdx.x & 31;

    const float* qkvb = qkv + (size_t)b * Ss * (3 * D);
    float2 qv = *(const float2*)(qkvb + (size_t)q * (3 * D) + h * DH + lane * 2);

    int r = rel[b * NINNER + (q - 1)];
    int kstart = g_gstart[b][r];
    int kend   = g_gstart[b][r + 1];

    float m = -1e30f, l = 0.f;
    float2 acc = make_float2(0.f, 0.f);

    for (int it = -1; it <= kend - kstart; it++) {
        int k;
        if (it == -1) k = 0;
        else if (it == kend - kstart) k = Ss - 1;
        else k = g_klist[b][kstart + it];

        const float* kp = qkvb + (size_t)k * (3 * D) + D + h * DH + lane * 2;
        float2 kv = *(const float2*)kp;
        float s = qv.x * kv.x + qv.y * kv.y;
        #pragma unroll
        for (int o = 16; o; o >>= 1) s += __shfl_xor_sync(0xFFFFFFFFu, s, o);
        s *= 0.125f;
        float mn = fmaxf(m, s);
        float corr = expf(m - mn);
        float p = expf(s - mn);
        float2 vv = *(const float2*)(kp + D);
        l = l * corr + p;
        acc.x = acc.x * corr + p * vv.x;
        acc.y = acc.y * corr + p * vv.y;
        m = mn;
    }
    float inv = 1.0f / l;
    *(float2*)(ao + ((size_t)b * Ss + q) * D + h * DH + lane * 2) =
        make_float2(acc.x * inv, acc.y * inv);
}

__global__ __launch_bounds__(256)
void attn_dense_part(const float* __restrict__ qkv,
                     const unsigned char* __restrict__ vmmask) {
    int chunk = blockIdx.x, qi = blockIdx.y, b = blockIdx.z;
    int h = threadIdx.x >> 5, lane = threadIdx.x & 31;
    int q = (qi == 0) ? 0 : Ss - 1;

    const float* qkvb = qkv + (size_t)b * Ss * (3 * D);
    const unsigned char* pb = vmmask + b * NVM;
    float2 qv = *(const float2*)(qkvb + (size_t)q * (3 * D) + h * DH + lane * 2);

    int k0 = chunk * DCH, k1 = min(Ss, k0 + DCH);
    float m = -1e30f, l = 0.f;
    float2 acc = make_float2(0.f, 0.f);

    for (int k = k0; k < k1; k++) {
        bool padded = (k >= 1 + NPM && k <= Ss - 2) && (pb[k - 1 - NPM] != 0);
        if (padded) continue;
        const float* kp = qkvb + (size_t)k * (3 * D) + D + h * DH + lane * 2;
        float2 kv = *(const float2*)kp;
        float s = qv.x * kv.x + qv.y * kv.y;
        #pragma unroll
        for (int o = 16; o; o >>= 1) s += __shfl_xor_sync(0xFFFFFFFFu, s, o);
        s *= 0.125f;
        float mn = fmaxf(m, s);
        float corr = expf(m - mn);
        float p = expf(s - mn);
        float2 vv = *(const float2*)(kp + D);
        l = l * corr + p;
        acc.x = acc.x * corr + p * vv.x;
        acc.y = acc.y * corr + p * vv.y;
        m = mn;
    }
    float* part = g_part[b][qi][h][chunk];
    if (lane == 0) { part[0] = m; part[1] = l; }
    part[2 + lane * 2]     = acc.x;
    part[2 + lane * 2 + 1] = acc.y;
}

__global__ __launch_bounds__(256)
void attn_dense_combine(float* __restrict__ ao) {
    int qi = blockIdx.x & 1, b = blockIdx.x >> 1;
    int h = threadIdx.x >> 5, lane = threadIdx.x & 31;
    int q = (qi == 0) ? 0 : Ss - 1;

    float M = -1e30f;
    #pragma unroll
    for (int c = 0; c < NCHUNK; c++) M = fmaxf(M, g_part[b][qi][h][c][0]);
    float L = 0.f;
    float2 acc = make_float2(0.f, 0.f);
    #pragma unroll
    for (int c = 0; c < NCHUNK; c++) {
        const float* part = g_part[b][qi][h][c];
        float w = expf(part[0] - M);
        L += part[1] * w;
        acc.x += w * part[2 + lane * 2];
        acc.y += w * part[2 + lane * 2 + 1];
    }
    float inv = 1.0f / L;
    *(float2*)(ao + ((size_t)b * Ss + q) * D + h * DH + lane * 2) =
        make_float2(acc.x * inv, acc.y * inv);
}

// ---------------- head -----------------------------------------------------
__global__ void head_kernel(const float* __restrict__ x,
                            const float* __restrict__ outW, const float* __restrict__ outb,
                            const float* __restrict__ crW,  const float* __restrict__ crb,
                            float* __restrict__ out) {
    int r = blockIdx.x;
    int tid = threadIdx.x;
    const float* w; const float* xr; float bias; int oidx;
    if (r < Bb * NVM) {
        int b = r / NVM, i = r % NVM;
        xr = x + ((size_t)b * Ss + 1 + NPM + i) * D;
        w = outW; bias = outb[0]; oidx = r;
    } else {
        int b = r - Bb * NVM;
        xr = x + ((size_t)b * Ss + Ss - 1) * D;
        w = crW; bias = crb[0]; oidx = Bb * NVM + b;
    }
    float s = 0.f;
    for (int c = tid; c < D; c += 128) s += xr[c] * w[c];
    #pragma unroll
    for (int o = 16; o; o >>= 1) s += __shfl_xor_sync(0xFFFFFFFFu, s, o);
    __shared__ float red[4];
    if ((tid & 31) == 0) red[tid >> 5] = s;
    __syncthreads();
    if (tid == 0) out[oidx] = red[0] + red[1] + red[2] + red[3] + bias;
}

// ---------------- launch ---------------------------------------------------
extern "C" void kernel_launch(void* const* d_in, const int* in_sizes, int n_in,
                              void* d_out, int out_size) {
    const float* vm_states = (const float*)d_in[0];
    const float* num_step  = (const float*)d_in[1];
    const float* pm_states = (const float*)d_in[2];
    const int*   rel       = (const int*)d_in[3];
    const unsigned char* vmmask = (const unsigned char*)d_in[4];
    const float* pm_W = (const float*)d_in[5];
    const float* pm_b = (const float*)d_in[6];
    const float* vm_W = (const float*)d_in[7];
    const float* vm_b = (const float*)d_in[8];
    const float* ln1_s = (const float*)d_in[9];
    const float* ln1_b = (const float*)d_in[10];
    const float* Wqkv = (const float*)d_in[11];
    const float* bqkv = (const float*)d_in[12];
    const float* Wo   = (const float*)d_in[13];
    const float* bo   = (const float*)d_in[14];
    const float* ln2_s = (const float*)d_in[15];
    const float* ln2_b = (const float*)d_in[16];
    const float* W1 = (const float*)d_in[17];
    const float* b1 = (const float*)d_in[18];
    const float* W2 = (const float*)d_in[19];
    const float* b2 = (const float*)d_in[20];
    const float* out_W = (const float*)d_in[21];
    const float* out_b = (const float*)d_in[22];
    const float* cr_W  = (const float*)d_in[23];
    const float* cr_b  = (const float*)d_in[24];

    float *xp, *hp, *qkvp, *aop, *ffnp;
    __nv_bfloat16 *whp, *wlp;
    cudaGetSymbolAddress((void**)&xp,   g_x);
    cudaGetSymbolAddress((void**)&hp,   g_h);
    cudaGetSymbolAddress((void**)&qkvp, g_qkv);
    cudaGetSymbolAddress((void**)&aop,  g_ao);
    cudaGetSymbolAddress((void**)&ffnp, g_ffn);
    cudaGetSymbolAddress((void**)&whp,  g_wh);
    cudaGetSymbolAddress((void**)&wlp,  g_wl);

    cudaFuncSetAttribute(mma_gemm, cudaFuncAttributeMaxDynamicSharedMemorySize, GSMEM);

    embed_kernel<<<MROWS, 128>>>(vm_states, num_step, pm_states, pm_W, pm_b, vm_W, vm_b, xp);
    build_groups<<<Bb, 256>>>(rel, vmmask);

    // pre-split+transpose all weights to bf16 hi/lo
    dim3 tb(32, 8);
    for (int l = 0; l < NL; l++) {
        size_t lo = (size_t)l * PERL;
        prep_w<<<dim3(3 * D / 32, D / 32), tb>>>(Wqkv + (size_t)l * D * 3 * D,
                                                 whp + lo + OQKV, wlp + lo + OQKV, D, 3 * D);
        prep_w<<<dim3(D / 32, D / 32), tb>>>(Wo + (size_t)l * D * D,
                                             whp + lo + OWO, wlp + lo + OWO, D, D);
        prep_w<<<dim3(DFF / 32, D / 32), tb>>>(W1 + (size_t)l * D * DFF,
                                               whp + lo + OW1, wlp + lo + OW1, D, DFF);
        prep_w<<<dim3(D / 32, DFF / 32), tb>>>(W2 + (size_t)l * DFF * D,
                                               whp + lo + OW2, wlp + lo + OW2, DFF, D);
    }

    const int M = MROWS;
    const int MT = (M + 127) / 128;
    dim3 gQKV(3 * D / 128, MT);
    dim3 gO(D / 128, MT);
    dim3 gF1(DFF / 128, MT);
    dim3 gSp(Ss, Bb);
    dim3 gDp(NCHUNK, 2, Bb);

    for (int l = 0; l < NL; l++) {
        size_t lo = (size_t)l * PERL;
        ln_kernel<<<M, 256>>>(xp, hp, ln1_s + l * D, ln1_b + l * D);
        mma_gemm<<<gQKV, 256, GSMEM>>>(hp, whp + lo + OQKV, wlp + lo + OQKV,
                                       bqkv + l * 3 * D, nullptr, qkvp, M, D, 3 * D, 0);
        attn_sparse<<<gSp, 256>>>(qkvp, rel, aop);
        attn_dense_part<<<gDp, 256>>>(qkvp, vmmask);
        attn_dense_combine<<<2 * Bb, 256>>>(aop);
        mma_gemm<<<gO, 256, GSMEM>>>(aop, whp + lo + OWO, wlp + lo + OWO,
                                     bo + l * D, xp, xp, M, D, D, 0);
        ln_kernel<<<M, 256>>>(xp, hp, ln2_s + l * D, ln2_b + l * D);
        mma_gemm<<<gF1, 256, GSMEM>>>(hp, whp + lo + OW1, wlp + lo + OW1,
                                      b1 + l * DFF, nullptr, ffnp, M, D, DFF, 1);
        mma_gemm<<<gO, 256, GSMEM>>>(ffnp, whp + lo + OW2, wlp + lo + OW2,
                                     b2 + l * D, xp, xp, M, DFF, D, 0);
    }

    head_kernel<<<Bb * NVM + Bb, 128>>>(xp, out_W, out_b, cr_W, cr_b, (float*)d_out);
}